// round 1
// baseline (speedup 1.0000x reference)
#include <cuda_runtime.h>
#include <math.h>

// ---------------- problem constants ----------------
#define B_    32
#define S_    160
#define KK_   44
#define E_    300
#define H_    256
#define V_    32000
#define G3_   768          // 3*H
#define NKEY_ 10240        // 2*B*S (keys_c ++ keys_r)
#define BS_   5120         // B*S

// ---------------- device scratch (static, no allocs) ----------------
__device__ float g_Pkey [V_ * 1536];        // [v][dir*768 + j]  (bias folded in)
__device__ float g_Penc [V_ * 1536];        // same, for encoder emb-part (bias folded)
__device__ float g_h    [2 * NKEY_ * H_];   // key GRU hidden, fwd/bwd
__device__ float g_gh   [2 * NKEY_ * G3_];  // key GRU gh temp
__device__ float g_ksum [NKEY_ * H_];       // hf + hb
__device__ float g_gienc[4 * BS_ * G3_];    // encoder input projections (x1f,x1b,x2f,x2b)
__device__ float g_eh   [4 * B_ * H_];      // encoder hidden per stream
__device__ float g_egh  [4 * B_ * G3_];     // encoder gh temp
__device__ float g_sc   [BS_ * 512];        // encoder outputs for x1 (of||ob)
__device__ float g_a    [BS_ * 512];
__device__ float g_energy[BS_];
__device__ float g_alpha [BS_];
__device__ float g_r    [B_ * 512];
__device__ float g_cattn[B_ * 512];

// ---------------- generic GEMM:  C = A(MxK) * W(NxK)^T (+bias) (+P[idx[m]] gather) ----------------
// BM=128 BN=64 BK=16, 256 threads, thread tile 8x4. M%128==0, N%64==0, K%4==0 assumed.
__global__ __launch_bounds__(256) void gemm_kernel(
    int M, int N, int K,
    const float* __restrict__ A, int lda,
    const float* __restrict__ W, int ldw,
    const float* __restrict__ bias,
    float* __restrict__ C, int ldc,
    const int* __restrict__ idx,
    const float* __restrict__ P, int ldP, int pOff)
{
    __shared__ float As[16][128];
    __shared__ float Ws[16][64];

    const int m0 = blockIdx.y * 128;
    const int n0 = blockIdx.x * 64;
    const int t  = threadIdx.x;
    const int tx = t & 15;           // 0..15 -> col group of 4
    const int ty = t >> 4;           // 0..15 -> row group of 8

    float acc[8][4];
#pragma unroll
    for (int i = 0; i < 8; i++)
#pragma unroll
        for (int j = 0; j < 4; j++) acc[i][j] = 0.f;

    for (int k0 = 0; k0 < K; k0 += 16) {
        // load A tile (128x16) as 512 float4, 2 per thread
#pragma unroll
        for (int i = 0; i < 2; i++) {
            int li  = t + i * 256;
            int row = li >> 2;
            int kq  = (li & 3) * 4;
            float4 v = make_float4(0.f, 0.f, 0.f, 0.f);
            if (k0 + kq < K)
                v = *(const float4*)(A + (size_t)(m0 + row) * lda + k0 + kq);
            As[kq + 0][row] = v.x; As[kq + 1][row] = v.y;
            As[kq + 2][row] = v.z; As[kq + 3][row] = v.w;
        }
        // load W tile (64x16) as 256 float4, 1 per thread
        {
            int row = t >> 2;
            int kq  = (t & 3) * 4;
            float4 v = make_float4(0.f, 0.f, 0.f, 0.f);
            if (k0 + kq < K)
                v = *(const float4*)(W + (size_t)(n0 + row) * ldw + k0 + kq);
            Ws[kq + 0][row] = v.x; Ws[kq + 1][row] = v.y;
            Ws[kq + 2][row] = v.z; Ws[kq + 3][row] = v.w;
        }
        __syncthreads();
#pragma unroll
        for (int kk = 0; kk < 16; kk++) {
            float4 a0 = *(const float4*)&As[kk][ty * 8];
            float4 a1 = *(const float4*)&As[kk][ty * 8 + 4];
            float4 w  = *(const float4*)&Ws[kk][tx * 4];
            float av[8] = {a0.x, a0.y, a0.z, a0.w, a1.x, a1.y, a1.z, a1.w};
            float wv[4] = {w.x, w.y, w.z, w.w};
#pragma unroll
            for (int i = 0; i < 8; i++)
#pragma unroll
                for (int j = 0; j < 4; j++) acc[i][j] += av[i] * wv[j];
        }
        __syncthreads();
    }

    // epilogue
    float addc[4] = {0.f, 0.f, 0.f, 0.f};
    if (bias) {
#pragma unroll
        for (int j = 0; j < 4; j++) addc[j] = bias[n0 + tx * 4 + j];
    }
#pragma unroll
    for (int i = 0; i < 8; i++) {
        int row = m0 + ty * 8 + i;
        float ga[4] = {0.f, 0.f, 0.f, 0.f};
        if (idx) {
            int v = idx[row];
            const float* pp = P + (size_t)v * ldP + pOff + n0 + tx * 4;
#pragma unroll
            for (int j = 0; j < 4; j++) ga[j] = pp[j];
        }
        float4 o;
        o.x = acc[i][0] + addc[0] + ga[0];
        o.y = acc[i][1] + addc[1] + ga[1];
        o.z = acc[i][2] + addc[2] + ga[2];
        o.w = acc[i][3] + addc[3] + ga[3];
        *(float4*)(C + (size_t)row * ldc + n0 + tx * 4) = o;
    }
}

static inline void gemm(int M, int N, int K,
                        const float* A, int lda,
                        const float* W, int ldw,
                        const float* bias,
                        float* C, int ldc,
                        const int* idx = nullptr, const float* P = nullptr,
                        int ldP = 0, int pOff = 0)
{
    dim3 grid(N / 64, M / 128);
    gemm_kernel<<<grid, 256>>>(M, N, K, A, lda, W, ldw, bias, C, ldc, idx, P, ldP, pOff);
}

// ---------------- zero ----------------
__global__ void zero_kernel(float* p, int n)
{
    for (int i = blockIdx.x * blockDim.x + threadIdx.x; i < n; i += gridDim.x * blockDim.x)
        p[i] = 0.f;
}

// ---------------- key GRU gates (both directions) ----------------
__device__ __forceinline__ float sigf(float x) { return 1.f / (1.f + expf(-x)); }

__global__ void key_gates_kernel(const int* __restrict__ keys_c,
                                 const int* __restrict__ keys_r, int t)
{
    int n   = blockIdx.x;        // 0..10239
    int c   = threadIdx.x;       // 0..255
    int dir = blockIdx.y;        // 0 fwd, 1 bwd
    int te  = (dir == 0) ? t : (KK_ - 1 - t);
    int key = (n < BS_) ? keys_c[n * KK_ + te] : keys_r[(n - BS_) * KK_ + te];

    const float* gi = g_Pkey + (size_t)key * 1536 + dir * 768;
    const float* gh = g_gh + (size_t)dir * NKEY_ * G3_ + (size_t)n * G3_;
    float*       h  = g_h  + (size_t)dir * NKEY_ * H_  + (size_t)n * H_;

    float ir = gi[c], iz = gi[256 + c], in = gi[512 + c];
    float hr = gh[c], hz = gh[256 + c], hn = gh[512 + c];
    float r  = sigf(ir + hr);
    float z  = sigf(iz + hz);
    float nn = tanhf(in + r * hn);
    float hp = h[c];
    h[c] = (1.f - z) * nn + z * hp;
}

__global__ void ksum_kernel()
{
    int i = blockIdx.x * blockDim.x + threadIdx.x;
    if (i < NKEY_ * H_) g_ksum[i] = g_h[i] + g_h[NKEY_ * H_ + i];
}

// ---------------- encoder recurrent gh: 4 streams, M=32, N=768, K=256 ----------------
__global__ __launch_bounds__(256) void enc_gh_kernel(const float* __restrict__ Whf,
                                                     const float* __restrict__ Whb,
                                                     const float* __restrict__ bhf,
                                                     const float* __restrict__ bhb)
{
    int st  = blockIdx.y;            // stream 0..3
    int n0c = blockIdx.x * 64;       // column tile
    const float* Wh = (st & 1) ? Whb : Whf;
    const float* bh = (st & 1) ? bhb : bhf;
    const float* h  = g_eh  + st * B_ * H_;
    float*       og = g_egh + st * B_ * G3_;

    __shared__ float Hs[32][32];   // [k][n]
    __shared__ float Ws[32][64];   // [k][c]

    int t  = threadIdx.x;
    int r0 = (t >> 5) * 4;         // 4 rows
    int c0 = (t & 31) * 2;         // 2 cols

    float acc[4][2];
#pragma unroll
    for (int i = 0; i < 4; i++) { acc[i][0] = 0.f; acc[i][1] = 0.f; }

    for (int k0 = 0; k0 < 256; k0 += 32) {
        {
            int n  = t >> 3;
            int kq = (t & 7) * 4;
            float4 v = *(const float4*)(h + n * 256 + k0 + kq);
            Hs[kq + 0][n] = v.x; Hs[kq + 1][n] = v.y;
            Hs[kq + 2][n] = v.z; Hs[kq + 3][n] = v.w;
        }
#pragma unroll
        for (int i = 0; i < 2; i++) {
            int li = t + i * 256;
            int cc = li >> 3;
            int kq = (li & 7) * 4;
            float4 v = *(const float4*)(Wh + (size_t)(n0c + cc) * 256 + k0 + kq);
            Ws[kq + 0][cc] = v.x; Ws[kq + 1][cc] = v.y;
            Ws[kq + 2][cc] = v.z; Ws[kq + 3][cc] = v.w;
        }
        __syncthreads();
#pragma unroll
        for (int kk = 0; kk < 32; kk++) {
            float4 a = *(const float4*)&Hs[kk][r0];
            float2 w = *(const float2*)&Ws[kk][c0];
            float av[4] = {a.x, a.y, a.z, a.w};
#pragma unroll
            for (int i = 0; i < 4; i++) {
                acc[i][0] += av[i] * w.x;
                acc[i][1] += av[i] * w.y;
            }
        }
        __syncthreads();
    }
#pragma unroll
    for (int i = 0; i < 4; i++) {
#pragma unroll
        for (int j = 0; j < 2; j++)
            og[(size_t)(r0 + i) * G3_ + n0c + c0 + j] = acc[i][j] + bh[n0c + c0 + j];
    }
}

// ---------------- encoder gates (4 streams) ----------------
__global__ void enc_gates_kernel(int t)
{
    int g   = blockIdx.x * blockDim.x + threadIdx.x;   // 4*32*256 = 32768
    int st  = g >> 13;
    int rem = g & 8191;
    int n   = rem >> 8;
    int c   = rem & 255;
    int s   = (st & 1) ? (S_ - 1 - t) : t;
    int row = n * S_ + s;

    const float* gi = g_gienc + (size_t)st * BS_ * G3_ + (size_t)row * G3_;
    const float* gh = g_egh   + st * B_ * G3_ + n * G3_;
    float*       h  = g_eh    + st * B_ * H_  + n * H_;

    float ir = gi[c], iz = gi[256 + c], in = gi[512 + c];
    float hr = gh[c], hz = gh[256 + c], hn = gh[512 + c];
    float r  = sigf(ir + hr);
    float z  = sigf(iz + hz);
    float nn = tanhf(in + r * hn);
    float hv = (1.f - z) * nn + z * h[c];
    h[c] = hv;
    if (st == 0)      g_sc[(size_t)row * 512 + c]       = hv;
    else if (st == 1) g_sc[(size_t)row * 512 + 256 + c] = hv;
}

__global__ void rcopy_kernel()
{
    int i = blockIdx.x * blockDim.x + threadIdx.x;   // 32*512
    int b = i >> 9, c = i & 511;
    g_r[i] = (c < 256) ? g_eh[2 * B_ * H_ + b * 256 + c]
                       : g_eh[3 * B_ * H_ + b * 256 + (c - 256)];
}

// ---------------- attention tail ----------------
__device__ __forceinline__ float blockReduceSum(float v)
{
    __shared__ float sh[32];
    for (int o = 16; o; o >>= 1) v += __shfl_down_sync(0xffffffffu, v, o);
    int lane = threadIdx.x & 31, w = threadIdx.x >> 5;
    if (lane == 0) sh[w] = v;
    __syncthreads();
    int nw = (blockDim.x + 31) >> 5;
    v = (w == 0 && lane < nw) ? sh[lane] : 0.f;
    if (w == 0)
        for (int o = 16; o; o >>= 1) v += __shfl_down_sync(0xffffffffu, v, o);
    return v;
}

__global__ void energy_kernel()
{
    int bs = blockIdx.x;
    int b  = bs / S_;
    float p = 0.f;
    for (int k = threadIdx.x; k < 512; k += 128)
        p += g_a[(size_t)bs * 512 + k] * g_r[b * 512 + k];
    float s = blockReduceSum(p);
    if (threadIdx.x == 0) g_energy[bs] = s;
}

__global__ void softmax_kernel(const float* __restrict__ mask)
{
    int b = blockIdx.x;
    __shared__ float ex[S_];
    __shared__ float smx, ssum;
    int tid = threadIdx.x;
    if (tid < S_) ex[tid] = g_energy[b * S_ + tid];
    __syncthreads();
    if (tid == 0) { float m = -1e30f; for (int s = 0; s < S_; s++) m = fmaxf(m, ex[s]); smx = m; }
    __syncthreads();
    if (tid < S_) ex[tid] = expf(ex[tid] - smx);
    __syncthreads();
    if (tid == 0) { float s = 0.f; for (int i = 0; i < S_; i++) s += ex[i]; ssum = s; }
    __syncthreads();
    if (tid < S_) g_alpha[b * S_ + tid] = ex[tid] / ssum * mask[b * S_ + tid];
}

__global__ void cattn_kernel()
{
    int b = blockIdx.x, d = threadIdx.x;
    float acc = 0.f;
    for (int s = 0; s < S_; s++)
        acc += g_alpha[b * S_ + s] * g_sc[(size_t)(b * S_ + s) * 512 + d];
    g_cattn[b * 512 + d] = acc;
}

__global__ void final_kernel(const float* __restrict__ Mm,
                             const float* __restrict__ b0,
                             float* __restrict__ out)
{
    int b = blockIdx.x;
    float part = 0.f;
    for (int d = threadIdx.x; d < 512; d += 256) {
        const float* mr = Mm + (size_t)d * 512;
        const float* rr = g_r + b * 512;
        float td = 0.f;
        for (int e = 0; e < 512; e++) td += mr[e] * rr[e];
        part += g_cattn[b * 512 + d] * td;
    }
    float s = blockReduceSum(part);
    if (threadIdx.x == 0) out[b] = s + b0[0];
}

// ---------------- host orchestration ----------------
extern "C" void kernel_launch(void* const* d_in, const int* in_sizes, int n_in,
                              void* d_out, int out_size)
{
    const int*   x1     = (const int*)d_in[0];
    const int*   x2     = (const int*)d_in[1];
    const int*   keys_c = (const int*)d_in[2];
    const int*   keys_r = (const int*)d_in[3];
    const float* x1mask = (const float*)d_in[4];
    const float* emb    = (const float*)d_in[5];
    const float* kWif   = (const float*)d_in[6];
    const float* kWhf   = (const float*)d_in[7];
    const float* kbif   = (const float*)d_in[8];
    const float* kbhf   = (const float*)d_in[9];
    const float* kWib   = (const float*)d_in[10];
    const float* kWhb   = (const float*)d_in[11];
    const float* kbib   = (const float*)d_in[12];
    const float* kbhb   = (const float*)d_in[13];
    const float* eWif   = (const float*)d_in[14];
    const float* eWhf   = (const float*)d_in[15];
    const float* ebif   = (const float*)d_in[16];
    const float* ebhf   = (const float*)d_in[17];
    const float* eWib   = (const float*)d_in[18];
    const float* eWhb   = (const float*)d_in[19];
    const float* ebib   = (const float*)d_in[20];
    const float* ebhb   = (const float*)d_in[21];
    const float* attn_W = (const float*)d_in[22];
    const float* attn_b = (const float*)d_in[23];
    const float* Mm     = (const float*)d_in[24];
    const float* b0     = (const float*)d_in[25];
    float* out = (float*)d_out;

    float *pPkey, *pPenc, *pH, *pGH, *pKsum, *pGienc, *pEh, *pSc, *pA;
    cudaGetSymbolAddress((void**)&pPkey,  g_Pkey);
    cudaGetSymbolAddress((void**)&pPenc,  g_Penc);
    cudaGetSymbolAddress((void**)&pH,     g_h);
    cudaGetSymbolAddress((void**)&pGH,    g_gh);
    cudaGetSymbolAddress((void**)&pKsum,  g_ksum);
    cudaGetSymbolAddress((void**)&pGienc, g_gienc);
    cudaGetSymbolAddress((void**)&pEh,    g_eh);
    cudaGetSymbolAddress((void**)&pSc,    g_sc);
    cudaGetSymbolAddress((void**)&pA,     g_a);

    // 1) vocabulary-level projection precompute (bias folded in)
    gemm(V_, 768, 300, emb, 300, kWif, 300, kbif, pPkey,       1536);
    gemm(V_, 768, 300, emb, 300, kWib, 300, kbib, pPkey + 768, 1536);
    gemm(V_, 768, 300, emb, 300, eWif, 556, ebif, pPenc,       1536);
    gemm(V_, 768, 300, emb, 300, eWib, 556, ebib, pPenc + 768, 1536);

    // 2) zero recurrent states
    zero_kernel<<<4096, 256>>>(pH, 2 * NKEY_ * H_);
    zero_kernel<<<16,   256>>>(pEh, 4 * B_ * H_);

    // 3) key BiGRU over 44 steps (both directions per step)
    for (int t = 0; t < KK_; t++) {
        gemm(NKEY_, G3_, H_, pH,               H_, kWhf, H_, kbhf, pGH,               G3_);
        gemm(NKEY_, G3_, H_, pH + NKEY_ * H_,  H_, kWhb, H_, kbhb, pGH + NKEY_ * G3_, G3_);
        key_gates_kernel<<<dim3(NKEY_, 2), 256>>>(keys_c, keys_r, t);
    }
    ksum_kernel<<<(NKEY_ * H_ + 255) / 256, 256>>>();

    // 4) encoder input projections (kc/kr GEMM + vocab gather of P_enc)
    gemm(BS_, G3_, H_, pKsum,            H_, eWif + 300, 556, nullptr, pGienc,                 G3_, x1, pPenc, 1536, 0);
    gemm(BS_, G3_, H_, pKsum,            H_, eWib + 300, 556, nullptr, pGienc + 1ll * BS_ * G3_, G3_, x1, pPenc, 1536, 768);
    gemm(BS_, G3_, H_, pKsum + BS_ * H_, H_, eWif + 300, 556, nullptr, pGienc + 2ll * BS_ * G3_, G3_, x2, pPenc, 1536, 0);
    gemm(BS_, G3_, H_, pKsum + BS_ * H_, H_, eWib + 300, 556, nullptr, pGienc + 3ll * BS_ * G3_, G3_, x2, pPenc, 1536, 768);

    // 5) encoder BiGRU over 160 steps (4 independent streams per step)
    for (int t = 0; t < S_; t++) {
        enc_gh_kernel<<<dim3(12, 4), 256>>>(eWhf, eWhb, ebhf, ebhb);
        enc_gates_kernel<<<128, 256>>>(t);
    }
    rcopy_kernel<<<64, 256>>>();

    // 6) attention + output
    gemm(BS_, 512, 512, pSc, 512, attn_W, 512, attn_b, pA, 512);
    energy_kernel<<<BS_, 128>>>();
    softmax_kernel<<<B_, 192>>>(x1mask);
    cattn_kernel<<<B_, 512>>>();
    final_kernel<<<B_, 256>>>(Mm, b0, out);
}